// round 5
// baseline (speedup 1.0000x reference)
#include <cuda_runtime.h>
#include <cstdint>
#include <cstddef>

// Problem dims (fixed by the dataset)
#define BB 16
#define TT 512
#define DD 256
#define HH 256
#define GG 1024        // 4H
#define NTOT 65536     // H*H
#define SCALE_ 0.1f

// ---------------------------------------------------------------------------
// Scratch (device-global: sanctioned alternative to cudaMalloc)
// ---------------------------------------------------------------------------
__device__ float g_Wx[(size_t)BB * TT * GG];             // 32 MB: x@W^T + b
__device__ float g_V0[(size_t)4096 * NTOT];              // 1 GB: V rows [0,4096)
__device__ float g_V1[(size_t)4096 * NTOT];              // 1 GB: V rows [4096,8192)
__device__ float g_hbuf[2][BB][HH];                      // double-buffered h

// ===========================================================================
// GEMM 1: V[m][o*256+h'] = sum_d x[m][d] * B_w[o][d][h']   (NN layout)
// A = x [8192 x 256] row-major.  For an n-tile, B slab = B_w + o*65536 + h0,
// layout [d][h'] row-major ld=256.  Tile 128x128, BK=16, double-buffered.
// ===========================================================================
__global__ __launch_bounds__(256) void gemm_v_kernel(
    const float* __restrict__ A, const float* __restrict__ Bw)
{
    __shared__ float As[2][16 * 132];
    __shared__ float Bs[2][16 * 132];
    const int tid = threadIdx.x;
    const int n0  = blockIdx.x * 128;          // global n in [0,65536)
    const int m0  = blockIdx.y * 128;
    const int o   = n0 >> 8;
    const int h0  = n0 & 255;
    const float* Bp = Bw + (size_t)o * NTOT + h0;   // [k][n] ld=256

    const int am = tid >> 1, ah = (tid & 1) * 8;    // A loader: row am, k-off ah
    const int bk = tid >> 4, bn = (tid & 15) * 8;   // B loader: k-row bk, n-off bn
    const int tx = tid & 15, ty = tid >> 4;

    const float* Aptr = A  + (size_t)(m0 + am) * DD + ah;
    const float* Bptr = Bp + (size_t)bk * 256 + bn;

    float4 a0r = *(const float4*)(Aptr);
    float4 a1r = *(const float4*)(Aptr + 4);
    float4 b0r = *(const float4*)(Bptr);
    float4 b1r = *(const float4*)(Bptr + 4);

    float acc[8][8];
#pragma unroll
    for (int i = 0; i < 8; i++)
#pragma unroll
        for (int j = 0; j < 8; j++) acc[i][j] = 0.f;

    {   // stage 0 -> smem (A transposed to [k][m])
        float av[8] = {a0r.x,a0r.y,a0r.z,a0r.w,a1r.x,a1r.y,a1r.z,a1r.w};
#pragma unroll
        for (int i = 0; i < 8; i++) As[0][(ah + i) * 132 + am] = av[i];
        *(float4*)&Bs[0][bk * 132 + bn]     = b0r;
        *(float4*)&Bs[0][bk * 132 + bn + 4] = b1r;
    }
    __syncthreads();

    int p = 0;
#pragma unroll 1
    for (int s = 0; s < 16; s++) {
        if (s < 15) {
            const int k0 = (s + 1) * 16;
            a0r = *(const float4*)(Aptr + k0);
            a1r = *(const float4*)(Aptr + k0 + 4);
            b0r = *(const float4*)(Bptr + (size_t)k0 * 256);
            b1r = *(const float4*)(Bptr + (size_t)k0 * 256 + 4);
        }
#pragma unroll
        for (int kk = 0; kk < 16; kk++) {
            float4 a0 = *(const float4*)&As[p][kk * 132 + ty * 4];
            float4 a1 = *(const float4*)&As[p][kk * 132 + 64 + ty * 4];
            float4 b0 = *(const float4*)&Bs[p][kk * 132 + tx * 4];
            float4 b1 = *(const float4*)&Bs[p][kk * 132 + 64 + tx * 4];
            float ar[8] = {a0.x,a0.y,a0.z,a0.w,a1.x,a1.y,a1.z,a1.w};
            float br[8] = {b0.x,b0.y,b0.z,b0.w,b1.x,b1.y,b1.z,b1.w};
#pragma unroll
            for (int i = 0; i < 8; i++)
#pragma unroll
                for (int j = 0; j < 8; j++) acc[i][j] += ar[i] * br[j];
        }
        if (s < 15) {
            __syncthreads();
            const int q = p ^ 1;
            float av[8] = {a0r.x,a0r.y,a0r.z,a0r.w,a1r.x,a1r.y,a1r.z,a1r.w};
#pragma unroll
            for (int i = 0; i < 8; i++) As[q][(ah + i) * 132 + am] = av[i];
            *(float4*)&Bs[q][bk * 132 + bn]     = b0r;
            *(float4*)&Bs[q][bk * 132 + bn + 4] = b1r;
            __syncthreads();
            p = q;
        }
    }

#pragma unroll
    for (int i = 0; i < 8; i++) {
        const int rr = (i < 4) ? (ty * 4 + i) : (64 + ty * 4 + (i - 4));
        const int m  = m0 + rr;
        float* Vb = (m < 4096 ? g_V0 : g_V1) + (size_t)(m & 4095) * NTOT + n0;
        *(float4*)&Vb[tx * 4]      = make_float4(acc[i][0], acc[i][1], acc[i][2], acc[i][3]);
        *(float4*)&Vb[64 + tx * 4] = make_float4(acc[i][4], acc[i][5], acc[i][6], acc[i][7]);
    }
}

// ===========================================================================
// GEMM 2: Wx[m][g] = sum_d x[m][d] * W_w[g][d] + W_b[g]   (NT layout)
// ===========================================================================
__global__ __launch_bounds__(256) void gemm_wx_kernel(
    const float* __restrict__ A, const float* __restrict__ Ww,
    const float* __restrict__ Wb)
{
    __shared__ float As[2][16 * 132];
    __shared__ float Bs[2][16 * 132];
    const int tid = threadIdx.x;
    const int n0  = blockIdx.x * 128;          // [0,1024)
    const int m0  = blockIdx.y * 128;

    const int am = tid >> 1, ah = (tid & 1) * 8;
    const int wn = tid >> 1, wh = (tid & 1) * 8;   // W loader: row wn, k-off wh
    const int tx = tid & 15, ty = tid >> 4;

    const float* Aptr = A  + (size_t)(m0 + am) * DD + ah;
    const float* Wptr = Ww + (size_t)(n0 + wn) * DD + wh;

    float4 a0r = *(const float4*)(Aptr);
    float4 a1r = *(const float4*)(Aptr + 4);
    float4 b0r = *(const float4*)(Wptr);
    float4 b1r = *(const float4*)(Wptr + 4);

    float acc[8][8];
#pragma unroll
    for (int i = 0; i < 8; i++)
#pragma unroll
        for (int j = 0; j < 8; j++) acc[i][j] = 0.f;

    {
        float av[8] = {a0r.x,a0r.y,a0r.z,a0r.w,a1r.x,a1r.y,a1r.z,a1r.w};
        float bv[8] = {b0r.x,b0r.y,b0r.z,b0r.w,b1r.x,b1r.y,b1r.z,b1r.w};
#pragma unroll
        for (int i = 0; i < 8; i++) {
            As[0][(ah + i) * 132 + am] = av[i];
            Bs[0][(wh + i) * 132 + wn] = bv[i];   // transpose W into [k][n]
        }
    }
    __syncthreads();

    int p = 0;
#pragma unroll 1
    for (int s = 0; s < 16; s++) {
        if (s < 15) {
            const int k0 = (s + 1) * 16;
            a0r = *(const float4*)(Aptr + k0);
            a1r = *(const float4*)(Aptr + k0 + 4);
            b0r = *(const float4*)(Wptr + k0);
            b1r = *(const float4*)(Wptr + k0 + 4);
        }
#pragma unroll
        for (int kk = 0; kk < 16; kk++) {
            float4 a0 = *(const float4*)&As[p][kk * 132 + ty * 4];
            float4 a1 = *(const float4*)&As[p][kk * 132 + 64 + ty * 4];
            float4 b0 = *(const float4*)&Bs[p][kk * 132 + tx * 4];
            float4 b1 = *(const float4*)&Bs[p][kk * 132 + 64 + tx * 4];
            float ar[8] = {a0.x,a0.y,a0.z,a0.w,a1.x,a1.y,a1.z,a1.w};
            float br[8] = {b0.x,b0.y,b0.z,b0.w,b1.x,b1.y,b1.z,b1.w};
#pragma unroll
            for (int i = 0; i < 8; i++)
#pragma unroll
                for (int j = 0; j < 8; j++) acc[i][j] += ar[i] * br[j];
        }
        if (s < 15) {
            __syncthreads();
            const int q = p ^ 1;
            float av[8] = {a0r.x,a0r.y,a0r.z,a0r.w,a1r.x,a1r.y,a1r.z,a1r.w};
            float bv[8] = {b0r.x,b0r.y,b0r.z,b0r.w,b1r.x,b1r.y,b1r.z,b1r.w};
#pragma unroll
            for (int i = 0; i < 8; i++) {
                As[q][(ah + i) * 132 + am] = av[i];
                Bs[q][(wh + i) * 132 + wn] = bv[i];
            }
            __syncthreads();
            p = q;
        }
    }

    float wb0[4], wb1[4];
#pragma unroll
    for (int j = 0; j < 4; j++) {
        wb0[j] = Wb[n0 + tx * 4 + j];
        wb1[j] = Wb[n0 + 64 + tx * 4 + j];
    }
#pragma unroll
    for (int i = 0; i < 8; i++) {
        const int rr = (i < 4) ? (ty * 4 + i) : (64 + ty * 4 + (i - 4));
        const int m  = m0 + rr;
        float* Wo = g_Wx + (size_t)m * GG + n0;
        *(float4*)&Wo[tx * 4] = make_float4(acc[i][0] + wb0[0], acc[i][1] + wb0[1],
                                            acc[i][2] + wb0[2], acc[i][3] + wb0[3]);
        *(float4*)&Wo[64 + tx * 4] = make_float4(acc[i][4] + wb1[0], acc[i][5] + wb1[1],
                                                 acc[i][6] + wb1[2], acc[i][7] + wb1[3]);
    }
}

// ===========================================================================
// Sequential scan. One 8-CTA cluster per batch (16 clusters, grid (8,16)).
// CTA r owns j in [32r, 32r+32): computes its i/f/o/g gate rows (U_w slice
// register-resident, 64 floats/thread at 512 threads) and its 32 m-rows
// (V streamed from HBM). h broadcast via global double buffer + cluster sync.
// ===========================================================================
__global__ void __cluster_dims__(8, 1, 1) __launch_bounds__(512, 1)
scan_kernel(const float* __restrict__ Uw, const float* __restrict__ Ub,
            const float* __restrict__ Bbias, float* __restrict__ out)
{
    __shared__ float h_sm[HH];
    __shared__ float gates_sm[128];
    __shared__ float m_sm[32];
    __shared__ float c_sm[32];
    __shared__ float bb_sm[32];

    const int r     = blockIdx.x;      // CTA rank in cluster
    const int b     = blockIdx.y;      // batch
    const int jbase = r * 32;
    const int t     = threadIdx.x;
    const int qt    = t & 3;           // quarter of the k-range for gates
    const int lg    = t >> 2;          // local gate row [0,128)
    const int row   = (lg >> 5) * HH + jbase + (lg & 31);  // global gate row
    const int r16   = t >> 4;          // m-row [0,32)
    const int l16   = t & 15;

    // register-resident U_w slice: 16 float4 covering k = 4*(i*4+qt)+[0,4)
    float4 U4[16];
#pragma unroll
    for (int i = 0; i < 16; i++)
        U4[i] = *(const float4*)&Uw[(size_t)row * HH + (size_t)(i * 4 + qt) * 4];
    const float ub = Ub[row];

    if (t < HH)  h_sm[t] = 0.f;
    if (t < 32) { c_sm[t] = 0.f; bb_sm[t] = Bbias[jbase + t]; }
    __syncthreads();

    const float4* h4 = (const float4*)h_sm;

    for (int step = 0; step < TT; step++) {
        // ---- V prefetch for this step (independent of h) ----
        const int mrow = b * TT + step;
        const float* Vb = (mrow < 4096 ? g_V0 : g_V1)
                          + (size_t)(mrow & 4095) * NTOT
                          + (size_t)(jbase + r16) * HH;
        const float4* V4 = (const float4*)Vb;
        float4 v[4];
#pragma unroll
        for (int e = 0; e < 4; e++) v[e] = V4[e * 16 + l16];

        float wx = 0.f;
        if (qt == 0) wx = g_Wx[(size_t)mrow * GG + row];

        // ---- gates: dot(U_row, h) split over 4 lanes ----
        float acc = 0.f;
#pragma unroll
        for (int i = 0; i < 16; i++) {
            float4 hh = h4[i * 4 + qt];
            float4 uu = U4[i];
            acc += hh.x * uu.x + hh.y * uu.y + hh.z * uu.z + hh.w * uu.w;
        }
        acc += __shfl_xor_sync(0xffffffffu, acc, 1);
        acc += __shfl_xor_sync(0xffffffffu, acc, 2);

        // ---- m: dot(V_row, h) split over 16 lanes ----
        float macc = 0.f;
#pragma unroll
        for (int e = 0; e < 4; e++) {
            float4 hh = h4[e * 16 + l16];
            macc += v[e].x * hh.x + v[e].y * hh.y + v[e].z * hh.z + v[e].w * hh.w;
        }
#pragma unroll
        for (int off = 8; off > 0; off >>= 1)
            macc += __shfl_xor_sync(0xffffffffu, macc, off);

        if (qt == 0)  gates_sm[lg] = acc + wx + ub;
        if (l16 == 0) m_sm[r16] = macc;
        __syncthreads();

        // ---- cell/hidden update for owned j's ----
        if (t < 32) {
            const int j = jbase + t;
            const float gi = gates_sm[t];
            const float gf = gates_sm[32 + t];
            const float go = gates_sm[64 + t];
            const float gg = gates_sm[96 + t];
            const float iv = 1.f / (1.f + __expf(-gi));
            const float fv = 1.f / (1.f + __expf(-gf));
            const float ov = 1.f / (1.f + __expf(-go));
            const float gv = tanhf(gg);
            const float mv = tanhf(m_sm[t] + bb_sm[t]);
            const float c  = fv * c_sm[t] + iv * gv + SCALE_ * mv;
            c_sm[t] = c;
            const float hn = ov * tanhf(c);
            g_hbuf[step & 1][b][j] = hn;
            out[((size_t)b * TT + step) * HH + j] = hn;
            if (step == TT - 1) {
                const size_t base = (size_t)BB * TT * HH;
                out[base + (size_t)b * HH + j] = hn;
                out[base + (size_t)BB * HH + (size_t)b * HH + j] = c;
            }
            __threadfence();
        }

        // ---- cluster-wide handoff of new h ----
        asm volatile("barrier.cluster.arrive.aligned;" ::: "memory");
        asm volatile("barrier.cluster.wait.aligned;"   ::: "memory");
        if (t < HH) h_sm[t] = g_hbuf[step & 1][b][t];
        __syncthreads();
    }
}

// ===========================================================================
// Launcher (graph-capturable: plain kernel launches on the caller's stream)
// ===========================================================================
extern "C" void kernel_launch(void* const* d_in, const int* in_sizes, int n_in,
                              void* d_out, int out_size)
{
    (void)in_sizes; (void)n_in; (void)out_size;
    const float* x   = (const float*)d_in[0];   // [16,512,256]
    const float* Ww  = (const float*)d_in[1];   // [1024,256]
    const float* Wb  = (const float*)d_in[2];   // [1024]
    const float* Uw  = (const float*)d_in[3];   // [1024,256]
    const float* Ub  = (const float*)d_in[4];   // [1024]
    const float* Bw  = (const float*)d_in[5];   // [256,256,256]
    const float* Bb  = (const float*)d_in[6];   // [256]
    float* out = (float*)d_out;                 // outs | h | c

    gemm_wx_kernel<<<dim3(GG / 128, (BB * TT) / 128), 256>>>(x, Ww, Wb);
    gemm_v_kernel<<<dim3(NTOT / 128, (BB * TT) / 128), 256>>>(x, Bw);
    scan_kernel<<<dim3(8, BB), 512>>>(Uw, Ub, Bb, out);
}

// round 6
// speedup vs baseline: 2.1399x; 2.1399x over previous
#include <cuda_runtime.h>
#include <cuda_fp16.h>
#include <cstdint>
#include <cstddef>

#define BB 16
#define TT 512
#define DD 256
#define HH 256
#define GG 1024
#define NTOT 65536
#define SCALE_ 0.1f

// ---------------- scratch (device globals, no cudaMalloc) ----------------
__device__ float  g_Wx[(size_t)BB * TT * GG];        // 32 MB
__device__ __half g_Vh[(size_t)BB * TT * NTOT];      // 1 GB fp16 V
__device__ __half g_xh[(size_t)BB * TT * DD];        // 4 MB  x in half
__device__ __half g_Bh[(size_t)HH * HH * DD];        // 32 MB B_w as [o][h'][d]
__device__ float  g_hbuf[2][BB][HH];

// ---------------- helpers ----------------
__device__ __forceinline__ void cp16(void* dst, const void* src) {
    uint32_t d = (uint32_t)__cvta_generic_to_shared(dst);
    asm volatile("cp.async.cg.shared.global [%0], [%1], 16;\n" :: "r"(d), "l"(src));
}
__device__ __forceinline__ void mma16816(float* d, const uint32_t* a, const uint32_t* b) {
    asm volatile(
        "mma.sync.aligned.m16n8k16.row.col.f32.f16.f16.f32 "
        "{%0,%1,%2,%3}, {%4,%5,%6,%7}, {%8,%9}, {%0,%1,%2,%3};\n"
        : "+f"(d[0]), "+f"(d[1]), "+f"(d[2]), "+f"(d[3])
        : "r"(a[0]), "r"(a[1]), "r"(a[2]), "r"(a[3]), "r"(b[0]), "r"(b[1]));
}

// ---------------- prep: x -> half ----------------
__global__ void conv_x_kernel(const float2* __restrict__ src) {
    __half2* dst = (__half2*)g_xh;
    const int n2 = BB * TT * DD / 2;
    for (int i = blockIdx.x * blockDim.x + threadIdx.x; i < n2;
         i += gridDim.x * blockDim.x) {
        float2 v = src[i];
        dst[i] = __floats2half2_rn(v.x, v.y);
    }
}

// ---------------- prep: B_w [o][d][h] f32 -> g_Bh [o][h][d] half ----------------
__global__ void transB_kernel(const float* __restrict__ Bw) {
    __shared__ float tile[32][33];
    const int o  = blockIdx.z;
    const int d0 = blockIdx.y * 32;
    const int h0 = blockIdx.x * 32;
    const int tx = threadIdx.x, ty = threadIdx.y;
    const float* src = Bw + (size_t)o * NTOT;
#pragma unroll
    for (int i = 0; i < 4; i++)
        tile[ty + i * 8][tx] = src[(size_t)(d0 + ty + i * 8) * HH + h0 + tx];
    __syncthreads();
    __half* dst = g_Bh + (size_t)o * NTOT;
#pragma unroll
    for (int i = 0; i < 4; i++)
        dst[(size_t)(h0 + ty + i * 8) * DD + d0 + tx] =
            __float2half_rn(tile[tx][ty + i * 8]);
}

// ===========================================================================
// Tensor-core V GEMM: V[m][o*256+h'] = sum_d x[m][d] * B_w[o][d][h']
// A = g_xh [8192][256] row-major (k contig), B = g_Bh [n][k] (k contig).
// Block 128x128, BK=32 halfs, 8 warps of 64x32. Output fp16.
// ===========================================================================
#define VPAD 40   // halfs per smem row (32 data + 8 pad); 80 B, 16B-aligned

__global__ __launch_bounds__(256) void gemm_v_mma(void) {
    __shared__ __half As[2][128 * VPAD];
    __shared__ __half Bs[2][128 * VPAD];

    const int tid = threadIdx.x;
    const int m0  = blockIdx.x * 128;          // 64 m-blocks (fast dim: L2 reuse of B)
    const int n0  = blockIdx.y * 128;          // 512 n-blocks
    const __half* Ag = g_xh + (size_t)m0 * DD;
    const __half* Bg = g_Bh + (size_t)n0 * DD; // [n][k], rows of 256 halfs

    // loader: idx in [0,512): row=idx>>2, quad=idx&3 (16B chunks of a 64B row)
    const int lrow = tid >> 2, lquad = (tid & 3) * 8;
    const int lrow2 = (tid + 256) >> 2, lquad2 = ((tid + 256) & 3) * 8;

    // fragment ids
    const int lane = tid & 31, w = tid >> 5;
    const int wm = (w & 1) * 64, wn = (w >> 1) * 32;
    const int fr = lane >> 2, fq = (lane & 3) * 2;

    float acc[4][4][4];
#pragma unroll
    for (int i = 0; i < 4; i++)
#pragma unroll
        for (int j = 0; j < 4; j++)
#pragma unroll
            for (int e = 0; e < 4; e++) acc[i][j][e] = 0.f;

    // preload tile 0
    cp16(&As[0][lrow * VPAD + lquad],   Ag + (size_t)lrow * DD + lquad);
    cp16(&As[0][lrow2 * VPAD + lquad2], Ag + (size_t)lrow2 * DD + lquad2);
    cp16(&Bs[0][lrow * VPAD + lquad],   Bg + (size_t)lrow * DD + lquad);
    cp16(&Bs[0][lrow2 * VPAD + lquad2], Bg + (size_t)lrow2 * DD + lquad2);
    asm volatile("cp.async.commit_group;\n");

#pragma unroll 1
    for (int kt = 0; kt < 8; kt++) {
        asm volatile("cp.async.wait_group 0;\n");
        __syncthreads();
        if (kt < 7) {
            const int ko = (kt + 1) * 32;
            const int buf = (kt + 1) & 1;
            cp16(&As[buf][lrow * VPAD + lquad],   Ag + (size_t)lrow * DD + ko + lquad);
            cp16(&As[buf][lrow2 * VPAD + lquad2], Ag + (size_t)lrow2 * DD + ko + lquad2);
            cp16(&Bs[buf][lrow * VPAD + lquad],   Bg + (size_t)lrow * DD + ko + lquad);
            cp16(&Bs[buf][lrow2 * VPAD + lquad2], Bg + (size_t)lrow2 * DD + ko + lquad2);
            asm volatile("cp.async.commit_group;\n");
        }
        const int p = kt & 1;
#pragma unroll
        for (int ks = 0; ks < 2; ks++) {
            uint32_t afr[4][4], bfr[4][2];
#pragma unroll
            for (int mt = 0; mt < 4; mt++) {
                const __half* ab = &As[p][(wm + mt * 16 + fr) * VPAD + ks * 16 + fq];
                afr[mt][0] = *(const uint32_t*)(ab);
                afr[mt][1] = *(const uint32_t*)(ab + 8 * VPAD);
                afr[mt][2] = *(const uint32_t*)(ab + 8);
                afr[mt][3] = *(const uint32_t*)(ab + 8 * VPAD + 8);
            }
#pragma unroll
            for (int nt = 0; nt < 4; nt++) {
                const __half* bb = &Bs[p][(wn + nt * 8 + fr) * VPAD + ks * 16 + fq];
                bfr[nt][0] = *(const uint32_t*)(bb);
                bfr[nt][1] = *(const uint32_t*)(bb + 8);
            }
#pragma unroll
            for (int mt = 0; mt < 4; mt++)
#pragma unroll
                for (int nt = 0; nt < 4; nt++)
                    mma16816(acc[mt][nt], afr[mt], bfr[nt]);
        }
    }

    // store fp16 (c frag: rows fr, fr+8; cols fq, fq+1)
#pragma unroll
    for (int mt = 0; mt < 4; mt++) {
        const int mA = m0 + wm + mt * 16 + fr;
#pragma unroll
        for (int nt = 0; nt < 4; nt++) {
            const int col = n0 + wn + nt * 8 + fq;
            *(__half2*)&g_Vh[(size_t)mA * NTOT + col] =
                __floats2half2_rn(acc[mt][nt][0], acc[mt][nt][1]);
            *(__half2*)&g_Vh[(size_t)(mA + 8) * NTOT + col] =
                __floats2half2_rn(acc[mt][nt][2], acc[mt][nt][3]);
        }
    }
}

// ===========================================================================
// GEMM 2 (fp32 SIMT, 100us): Wx = x @ W^T + b
// ===========================================================================
__global__ __launch_bounds__(256) void gemm_wx_kernel(
    const float* __restrict__ A, const float* __restrict__ Ww,
    const float* __restrict__ Wb)
{
    __shared__ float As[2][16 * 132];
    __shared__ float Bs[2][16 * 132];
    const int tid = threadIdx.x;
    const int n0  = blockIdx.x * 128;
    const int m0  = blockIdx.y * 128;
    const int am = tid >> 1, ah = (tid & 1) * 8;
    const int tx = tid & 15, ty = tid >> 4;
    const float* Aptr = A  + (size_t)(m0 + am) * DD + ah;
    const float* Wptr = Ww + (size_t)(n0 + am) * DD + ah;

    float4 a0r = *(const float4*)(Aptr);
    float4 a1r = *(const float4*)(Aptr + 4);
    float4 b0r = *(const float4*)(Wptr);
    float4 b1r = *(const float4*)(Wptr + 4);

    float acc[8][8];
#pragma unroll
    for (int i = 0; i < 8; i++)
#pragma unroll
        for (int j = 0; j < 8; j++) acc[i][j] = 0.f;

    {
        float av[8] = {a0r.x,a0r.y,a0r.z,a0r.w,a1r.x,a1r.y,a1r.z,a1r.w};
        float bv[8] = {b0r.x,b0r.y,b0r.z,b0r.w,b1r.x,b1r.y,b1r.z,b1r.w};
#pragma unroll
        for (int i = 0; i < 8; i++) {
            As[0][(ah + i) * 132 + am] = av[i];
            Bs[0][(ah + i) * 132 + am] = bv[i];
        }
    }
    __syncthreads();

    int p = 0;
#pragma unroll 1
    for (int s = 0; s < 16; s++) {
        if (s < 15) {
            const int k0 = (s + 1) * 16;
            a0r = *(const float4*)(Aptr + k0);
            a1r = *(const float4*)(Aptr + k0 + 4);
            b0r = *(const float4*)(Wptr + k0);
            b1r = *(const float4*)(Wptr + k0 + 4);
        }
#pragma unroll
        for (int kk = 0; kk < 16; kk++) {
            float4 a0 = *(const float4*)&As[p][kk * 132 + ty * 4];
            float4 a1 = *(const float4*)&As[p][kk * 132 + 64 + ty * 4];
            float4 b0 = *(const float4*)&Bs[p][kk * 132 + tx * 4];
            float4 b1 = *(const float4*)&Bs[p][kk * 132 + 64 + tx * 4];
            float ar[8] = {a0.x,a0.y,a0.z,a0.w,a1.x,a1.y,a1.z,a1.w};
            float br[8] = {b0.x,b0.y,b0.z,b0.w,b1.x,b1.y,b1.z,b1.w};
#pragma unroll
            for (int i = 0; i < 8; i++)
#pragma unroll
                for (int j = 0; j < 8; j++) acc[i][j] += ar[i] * br[j];
        }
        if (s < 15) {
            __syncthreads();
            const int q = p ^ 1;
            float av[8] = {a0r.x,a0r.y,a0r.z,a0r.w,a1r.x,a1r.y,a1r.z,a1r.w};
            float bv[8] = {b0r.x,b0r.y,b0r.z,b0r.w,b1r.x,b1r.y,b1r.z,b1r.w};
#pragma unroll
            for (int i = 0; i < 8; i++) {
                As[q][(ah + i) * 132 + am] = av[i];
                Bs[q][(ah + i) * 132 + am] = bv[i];
            }
            __syncthreads();
            p = q;
        }
    }

    float wb0[4], wb1[4];
#pragma unroll
    for (int j = 0; j < 4; j++) {
        wb0[j] = Wb[n0 + tx * 4 + j];
        wb1[j] = Wb[n0 + 64 + tx * 4 + j];
    }
#pragma unroll
    for (int i = 0; i < 8; i++) {
        const int rr = (i < 4) ? (ty * 4 + i) : (64 + ty * 4 + (i - 4));
        float* Wo = g_Wx + (size_t)(m0 + rr) * GG + n0;
        *(float4*)&Wo[tx * 4] = make_float4(acc[i][0] + wb0[0], acc[i][1] + wb0[1],
                                            acc[i][2] + wb0[2], acc[i][3] + wb0[3]);
        *(float4*)&Wo[64 + tx * 4] = make_float4(acc[i][4] + wb1[0], acc[i][5] + wb1[1],
                                                 acc[i][6] + wb1[2], acc[i][7] + wb1[3]);
    }
}

// ===========================================================================
// Scan: 8-CTA cluster per batch; V fp16, next-step V prefetched before barrier.
// ===========================================================================
__global__ void __cluster_dims__(8, 1, 1) __launch_bounds__(512, 1)
scan_kernel(const float* __restrict__ Uw, const float* __restrict__ Ub,
            const float* __restrict__ Bbias, float* __restrict__ out)
{
    __shared__ float h_sm[HH];
    __shared__ float gates_sm[128];
    __shared__ float m_sm[32];
    __shared__ float c_sm[32];
    __shared__ float bb_sm[32];

    const int r     = blockIdx.x;
    const int b     = blockIdx.y;
    const int jbase = r * 32;
    const int t     = threadIdx.x;
    const int qt    = t & 3;
    const int lg    = t >> 2;
    const int row   = (lg >> 5) * HH + jbase + (lg & 31);
    const int r16   = t >> 4;
    const int l16   = t & 15;

    float4 U4[16];
#pragma unroll
    for (int i = 0; i < 16; i++)
        U4[i] = *(const float4*)&Uw[(size_t)row * HH + (size_t)(i * 4 + qt) * 4];
    const float ub = Ub[row];

    if (t < HH)  h_sm[t] = 0.f;
    if (t < 32) { c_sm[t] = 0.f; bb_sm[t] = Bbias[jbase + t]; }
    __syncthreads();

    const float4* h4 = (const float4*)h_sm;
    const size_t vrow_off = (size_t)(jbase + r16) * HH + (size_t)l16 * 16;

    // preload V for step 0
    uint4 v0 = *(const uint4*)(g_Vh + (size_t)(b * TT) * NTOT + vrow_off);
    uint4 v1 = *(const uint4*)(g_Vh + (size_t)(b * TT) * NTOT + vrow_off + 8);

    for (int step = 0; step < TT; step++) {
        const int mrow = b * TT + step;
        float wx = 0.f;
        if (qt == 0) wx = g_Wx[(size_t)mrow * GG + row];

        // gates: dot(U_row, h), 4 lanes
        float acc = 0.f;
#pragma unroll
        for (int i = 0; i < 16; i++) {
            float4 hh = h4[i * 4 + qt];
            float4 uu = U4[i];
            acc += hh.x * uu.x + hh.y * uu.y + hh.z * uu.z + hh.w * uu.w;
        }
        acc += __shfl_xor_sync(0xffffffffu, acc, 1);
        acc += __shfl_xor_sync(0xffffffffu, acc, 2);

        // m: dot(V_row fp16, h), 16 lanes, 16 consecutive k per lane
        float macc = 0.f;
        {
            const __half2* vh0 = (const __half2*)&v0;
            const __half2* vh1 = (const __half2*)&v1;
            float4 ha = h4[l16 * 4 + 0];
            float4 hbv = h4[l16 * 4 + 1];
            float4 hc = h4[l16 * 4 + 2];
            float4 hd = h4[l16 * 4 + 3];
            float2 p;
            p = __half22float2(vh0[0]); macc += p.x * ha.x  + p.y * ha.y;
            p = __half22float2(vh0[1]); macc += p.x * ha.z  + p.y * ha.w;
            p = __half22float2(vh0[2]); macc += p.x * hbv.x + p.y * hbv.y;
            p = __half22float2(vh0[3]); macc += p.x * hbv.z + p.y * hbv.w;
            p = __half22float2(vh1[0]); macc += p.x * hc.x  + p.y * hc.y;
            p = __half22float2(vh1[1]); macc += p.x * hc.z  + p.y * hc.w;
            p = __half22float2(vh1[2]); macc += p.x * hd.x  + p.y * hd.y;
            p = __half22float2(vh1[3]); macc += p.x * hd.z  + p.y * hd.w;
        }
        // prefetch next step's V (h-independent) to hide DRAM under the barrier
        const int nrow = (step + 1 < TT) ? (mrow + 1) : mrow;
        v0 = *(const uint4*)(g_Vh + (size_t)nrow * NTOT + vrow_off);
        v1 = *(const uint4*)(g_Vh + (size_t)nrow * NTOT + vrow_off + 8);

#pragma unroll
        for (int off = 8; off > 0; off >>= 1)
            macc += __shfl_xor_sync(0xffffffffu, macc, off);

        if (qt == 0)  gates_sm[lg] = acc + wx + ub;
        if (l16 == 0) m_sm[r16] = macc;
        __syncthreads();

        if (t < 32) {
            const int j = jbase + t;
            const float gi = gates_sm[t];
            const float gf = gates_sm[32 + t];
            const float go = gates_sm[64 + t];
            const float gg = gates_sm[96 + t];
            const float iv = 1.f / (1.f + __expf(-gi));
            const float fv = 1.f / (1.f + __expf(-gf));
            const float ov = 1.f / (1.f + __expf(-go));
            const float gv = tanhf(gg);
            const float mv = tanhf(m_sm[t] + bb_sm[t]);
            const float c  = fv * c_sm[t] + iv * gv + SCALE_ * mv;
            c_sm[t] = c;
            const float hn = ov * tanhf(c);
            g_hbuf[step & 1][b][j] = hn;
            out[((size_t)b * TT + step) * HH + j] = hn;
            if (step == TT - 1) {
                const size_t base = (size_t)BB * TT * HH;
                out[base + (size_t)b * HH + j] = hn;
                out[base + (size_t)BB * HH + (size_t)b * HH + j] = c;
            }
            __threadfence();
        }

        asm volatile("barrier.cluster.arrive.aligned;" ::: "memory");
        asm volatile("barrier.cluster.wait.aligned;"   ::: "memory");
        if (t < HH) h_sm[t] = g_hbuf[step & 1][b][t];
        __syncthreads();
    }
}

// ===========================================================================
// Launcher
// ===========================================================================
extern "C" void kernel_launch(void* const* d_in, const int* in_sizes, int n_in,
                              void* d_out, int out_size)
{
    (void)in_sizes; (void)n_in; (void)out_size;
    const float* x   = (const float*)d_in[0];
    const float* Ww  = (const float*)d_in[1];
    const float* Wb  = (const float*)d_in[2];
    const float* Uw  = (const float*)d_in[3];
    const float* Ub  = (const float*)d_in[4];
    const float* Bw  = (const float*)d_in[5];
    const float* Bb  = (const float*)d_in[6];
    float* out = (float*)d_out;

    conv_x_kernel<<<1024, 256>>>((const float2*)x);
    transB_kernel<<<dim3(8, 8, 256), dim3(32, 8)>>>(Bw);
    gemm_wx_kernel<<<dim3(GG / 128, (BB * TT) / 128), 256>>>(x, Ww, Wb);
    gemm_v_mma<<<dim3(64, 512), 256>>>();
    scan_kernel<<<dim3(8, BB), 512>>>(Uw, Ub, Bb, out);
}

// round 8
// speedup vs baseline: 2.3381x; 1.0926x over previous
#include <cuda_runtime.h>
#include <cuda_fp16.h>
#include <cstdint>
#include <cstddef>

#define BB 16
#define TT 512
#define DD 256
#define HH 256
#define GG 1024
#define NTOT 65536
#define SCALE_ 0.1f

// ---------------- scratch (device globals, no cudaMalloc) ----------------
__device__ float  g_Wx[(size_t)BB * TT * GG];        // 32 MB
__device__ __half g_Vh[(size_t)BB * TT * NTOT];      // 1 GB fp16 V
__device__ __half g_xh[(size_t)BB * TT * DD];        // 4 MB  x in half
__device__ __half g_Bh[(size_t)HH * HH * DD];        // 32 MB B_w as [o][h'][d]
__device__ float  g_hbuf[2][BB][HH];

// ---------------- helpers ----------------
__device__ __forceinline__ uint32_t smem_u32(const void* p) {
    return (uint32_t)__cvta_generic_to_shared(p);
}
__device__ __forceinline__ void cp16s(uint32_t dst, const void* src) {
    asm volatile("cp.async.cg.shared.global [%0], [%1], 16;" :: "r"(dst), "l"(src));
}
__device__ __forceinline__ void ldsm4(uint32_t* r, uint32_t a) {
    asm volatile("ldmatrix.sync.aligned.m8n8.x4.shared.b16 {%0,%1,%2,%3}, [%4];"
        : "=r"(r[0]), "=r"(r[1]), "=r"(r[2]), "=r"(r[3]) : "r"(a));
}
__device__ __forceinline__ void mma16816(float* d, const uint32_t* a, const uint32_t* b) {
    asm volatile(
        "mma.sync.aligned.m16n8k16.row.col.f32.f16.f16.f32 "
        "{%0,%1,%2,%3}, {%4,%5,%6,%7}, {%8,%9}, {%0,%1,%2,%3};\n"
        : "+f"(d[0]), "+f"(d[1]), "+f"(d[2]), "+f"(d[3])
        : "r"(a[0]), "r"(a[1]), "r"(a[2]), "r"(a[3]), "r"(b[0]), "r"(b[1]));
}

// ---------------- prep: x -> half ----------------
__global__ void conv_x_kernel(const float2* __restrict__ src) {
    __half2* dst = (__half2*)g_xh;
    const int n2 = BB * TT * DD / 2;
    for (int i = blockIdx.x * blockDim.x + threadIdx.x; i < n2;
         i += gridDim.x * blockDim.x) {
        float2 v = src[i];
        dst[i] = __floats2half2_rn(v.x, v.y);
    }
}

// ---------------- prep: B_w [o][d][h] f32 -> g_Bh [o][h][d] half ----------------
__global__ void transB_kernel(const float* __restrict__ Bw) {
    __shared__ float tile[32][33];
    const int o  = blockIdx.z;
    const int d0 = blockIdx.y * 32;
    const int h0 = blockIdx.x * 32;
    const int tx = threadIdx.x, ty = threadIdx.y;
    const float* src = Bw + (size_t)o * NTOT;
#pragma unroll
    for (int i = 0; i < 4; i++)
        tile[ty + i * 8][tx] = src[(size_t)(d0 + ty + i * 8) * HH + h0 + tx];
    __syncthreads();
    __half* dst = g_Bh + (size_t)o * NTOT;
#pragma unroll
    for (int i = 0; i < 4; i++)
        dst[(size_t)(h0 + ty + i * 8) * DD + d0 + tx] =
            __float2half_rn(tile[tx][ty + i * 8]);
}

// ===========================================================================
// HMMA V GEMM: V[m][o*256+h'] = sum_d x[m][d] * B_w[o][d][h']
// Tile 256x128, BK=64 halfs (128B rows), SW128-swizzled smem (no padding),
// 3-stage cp.async pipeline, ldmatrix.x4 fragment loads, 8 warps of 64x64.
// A = g_xh [8192][256] (k contig), B = g_Bh [n][k] (k contig). Output fp16.
// ===========================================================================
#define VBM 256
#define VBN 128
#define ASTG (VBM * 128)          // 32768 B per stage
#define BSTG (VBN * 128)          // 16384 B per stage
#define STG  (ASTG + BSTG)        // 49152 B
#define VSMEM (3 * STG)           // 147456 B

__global__ void __launch_bounds__(256, 1) gemm_v_mma(void) {
    extern __shared__ char smem[];
    const uint32_t sb = smem_u32(smem);
    const int tid  = threadIdx.x;
    const int lane = tid & 31;
    const int w    = tid >> 5;

    const int m0 = blockIdx.x * VBM;   // 32 m-blocks (fast: B slab L2 reuse)
    const int n0 = blockIdx.y * VBN;   // 512 n-blocks
    const __half* Ag = g_xh + (size_t)m0 * DD;
    const __half* Bg = g_Bh + (size_t)n0 * DD;

    // warp tile: 4 warps along m, 2 along n
    const int wm = (w & 3) * 64;
    const int wn = (w >> 2) * 64;

    // ---- loader constants (per 16B chunk: row r, chunk c -> swizzled) ----
    // A: 2048 chunks; B: 1024 chunks. thread t does chunk t+256*i.
    // ---- fragment address constants ----
    const int a_row = wm + (lane & 15);               // + mt*16
    const int a_rx  = ((a_row & 7) * 16);
    const int a_xo  = ((lane >> 4) & 1) * 16;
    const int b_row = wn + (lane & 7) + ((lane >> 4) & 1) * 8;  // + nt2*16
    const int b_rx  = ((b_row & 7) * 16);
    const int b_xo  = ((lane >> 3) & 1) * 16;

    float acc[4][8][4];
#pragma unroll
    for (int i = 0; i < 4; i++)
#pragma unroll
        for (int j = 0; j < 8; j++)
#pragma unroll
            for (int e = 0; e < 4; e++) acc[i][j][e] = 0.f;

    // ---- issue loads for a stage ----
    auto load_stage = [&](int kc, int stg) {
        const uint32_t sA = sb + stg * STG;
        const uint32_t sB = sA + ASTG;
        const __half* As = Ag + kc * 64;
        const __half* Bs2 = Bg + kc * 64;
#pragma unroll
        for (int i = 0; i < 8; i++) {
            const int idx = tid + 256 * i;
            const int r = idx >> 3, c = idx & 7;
            const uint32_t d = r * 128 + ((c * 16) ^ ((r & 7) * 16));
            cp16s(sA + d, As + (size_t)r * DD + c * 8);
        }
#pragma unroll
        for (int i = 0; i < 4; i++) {
            const int idx = tid + 256 * i;
            const int r = idx >> 3, c = idx & 7;
            const uint32_t d = r * 128 + ((c * 16) ^ ((r & 7) * 16));
            cp16s(sB + d, Bs2 + (size_t)r * DD + c * 8);
        }
        asm volatile("cp.async.commit_group;");
    };

    load_stage(0, 0);
    load_stage(1, 1);

#pragma unroll
    for (int kc = 0; kc < 4; kc++) {
        if (kc < 3) asm volatile("cp.async.wait_group 1;");
        else        asm volatile("cp.async.wait_group 0;");
        __syncthreads();
        if (kc < 2) load_stage(kc + 2, (kc + 2) % 3);

        const uint32_t sA = sb + (kc % 3) * STG;
        const uint32_t sB = sA + ASTG;
#pragma unroll
        for (int ks = 0; ks < 4; ks++) {
            uint32_t afr[4][4], bfr[4][4];
#pragma unroll
            for (int mt = 0; mt < 4; mt++) {
                const int r = a_row + mt * 16;
                ldsm4(afr[mt], sA + r * 128 + ((ks * 32 + a_xo) ^ a_rx));
            }
#pragma unroll
            for (int nt2 = 0; nt2 < 4; nt2++) {
                const int r = b_row + nt2 * 16;
                ldsm4(bfr[nt2], sB + r * 128 + ((ks * 32 + b_xo) ^ b_rx));
            }
#pragma unroll
            for (int mt = 0; mt < 4; mt++)
#pragma unroll
                for (int nt = 0; nt < 8; nt++)
                    mma16816(acc[mt][nt], afr[mt], &bfr[nt >> 1][(nt & 1) * 2]);
        }
        __syncthreads();
    }

    // ---- store fp16 (c frag rows fr, fr+8; cols fq, fq+1) ----
    const int fr = lane >> 2, fq = (lane & 3) * 2;
#pragma unroll
    for (int mt = 0; mt < 4; mt++) {
        const int mA = m0 + wm + mt * 16 + fr;
#pragma unroll
        for (int nt = 0; nt < 8; nt++) {
            const int col = n0 + wn + nt * 8 + fq;
            *(__half2*)&g_Vh[(size_t)mA * NTOT + col] =
                __floats2half2_rn(acc[mt][nt][0], acc[mt][nt][1]);
            *(__half2*)&g_Vh[(size_t)(mA + 8) * NTOT + col] =
                __floats2half2_rn(acc[mt][nt][2], acc[mt][nt][3]);
        }
    }
}

// ===========================================================================
// GEMM 2 (fp32 SIMT): Wx = x @ W^T + b
// ===========================================================================
__global__ __launch_bounds__(256) void gemm_wx_kernel(
    const float* __restrict__ A, const float* __restrict__ Ww,
    const float* __restrict__ Wb)
{
    __shared__ float As[2][16 * 132];
    __shared__ float Bs[2][16 * 132];
    const int tid = threadIdx.x;
    const int n0  = blockIdx.x * 128;
    const int m0  = blockIdx.y * 128;
    const int am = tid >> 1, ah = (tid & 1) * 8;
    const int tx = tid & 15, ty = tid >> 4;
    const float* Aptr = A  + (size_t)(m0 + am) * DD + ah;
    const float* Wptr = Ww + (size_t)(n0 + am) * DD + ah;

    float4 a0r = *(const float4*)(Aptr);
    float4 a1r = *(const float4*)(Aptr + 4);
    float4 b0r = *(const float4*)(Wptr);
    float4 b1r = *(const float4*)(Wptr + 4);

    float acc[8][8];
#pragma unroll
    for (int i = 0; i < 8; i++)
#pragma unroll
        for (int j = 0; j < 8; j++) acc[i][j] = 0.f;

    {
        float av[8] = {a0r.x,a0r.y,a0r.z,a0r.w,a1r.x,a1r.y,a1r.z,a1r.w};
        float bv[8] = {b0r.x,b0r.y,b0r.z,b0r.w,b1r.x,b1r.y,b1r.z,b1r.w};
#pragma unroll
        for (int i = 0; i < 8; i++) {
            As[0][(ah + i) * 132 + am] = av[i];
            Bs[0][(ah + i) * 132 + am] = bv[i];
        }
    }
    __syncthreads();

    int p = 0;
#pragma unroll 1
    for (int s = 0; s < 16; s++) {
        if (s < 15) {
            const int k0 = (s + 1) * 16;
            a0r = *(const float4*)(Aptr + k0);
            a1r = *(const float4*)(Aptr + k0 + 4);
            b0r = *(const float4*)(Wptr + k0);
            b1r = *(const float4*)(Wptr + k0 + 4);
        }
#pragma unroll
        for (int kk = 0; kk < 16; kk++) {
            float4 a0 = *(const float4*)&As[p][kk * 132 + ty * 4];
            float4 a1 = *(const float4*)&As[p][kk * 132 + 64 + ty * 4];
            float4 b0 = *(const float4*)&Bs[p][kk * 132 + tx * 4];
            float4 b1 = *(const float4*)&Bs[p][kk * 132 + 64 + tx * 4];
            float ar[8] = {a0.x,a0.y,a0.z,a0.w,a1.x,a1.y,a1.z,a1.w};
            float br[8] = {b0.x,b0.y,b0.z,b0.w,b1.x,b1.y,b1.z,b1.w};
#pragma unroll
            for (int i = 0; i < 8; i++)
#pragma unroll
                for (int j = 0; j < 8; j++) acc[i][j] += ar[i] * br[j];
        }
        if (s < 15) {
            __syncthreads();
            const int q = p ^ 1;
            float av[8] = {a0r.x,a0r.y,a0r.z,a0r.w,a1r.x,a1r.y,a1r.z,a1r.w};
            float bv[8] = {b0r.x,b0r.y,b0r.z,b0r.w,b1r.x,b1r.y,b1r.z,b1r.w};
#pragma unroll
            for (int i = 0; i < 8; i++) {
                As[q][(ah + i) * 132 + am] = av[i];
                Bs[q][(ah + i) * 132 + am] = bv[i];
            }
            __syncthreads();
            p = q;
        }
    }

    float wb0[4], wb1[4];
#pragma unroll
    for (int j = 0; j < 4; j++) {
        wb0[j] = Wb[n0 + tx * 4 + j];
        wb1[j] = Wb[n0 + 64 + tx * 4 + j];
    }
#pragma unroll
    for (int i = 0; i < 8; i++) {
        const int rr = (i < 4) ? (ty * 4 + i) : (64 + ty * 4 + (i - 4));
        float* Wo = g_Wx + (size_t)(m0 + rr) * GG + n0;
        *(float4*)&Wo[tx * 4] = make_float4(acc[i][0] + wb0[0], acc[i][1] + wb0[1],
                                            acc[i][2] + wb0[2], acc[i][3] + wb0[3]);
        *(float4*)&Wo[64 + tx * 4] = make_float4(acc[i][4] + wb1[0], acc[i][5] + wb1[1],
                                                 acc[i][6] + wb1[2], acc[i][7] + wb1[3]);
    }
}

// ===========================================================================
// Scan: 8-CTA cluster per batch; V fp16, next-step V prefetched early.
// ===========================================================================
__global__ void __cluster_dims__(8, 1, 1) __launch_bounds__(512, 1)
scan_kernel(const float* __restrict__ Uw, const float* __restrict__ Ub,
            const float* __restrict__ Bbias, float* __restrict__ out)
{
    __shared__ float h_sm[HH];
    __shared__ float gates_sm[128];
    __shared__ float m_sm[32];
    __shared__ float c_sm[32];
    __shared__ float bb_sm[32];

    const int r     = blockIdx.x;
    const int b     = blockIdx.y;
    const int jbase = r * 32;
    const int t     = threadIdx.x;
    const int qt    = t & 3;
    const int lg    = t >> 2;
    const int row   = (lg >> 5) * HH + jbase + (lg & 31);
    const int r16   = t >> 4;
    const int l16   = t & 15;

    float4 U4[16];
#pragma unroll
    for (int i = 0; i < 16; i++)
        U4[i] = *(const float4*)&Uw[(size_t)row * HH + (size_t)(i * 4 + qt) * 4];
    const float ub = Ub[row];

    if (t < HH)  h_sm[t] = 0.f;
    if (t < 32) { c_sm[t] = 0.f; bb_sm[t] = Bbias[jbase + t]; }
    __syncthreads();

    const float4* h4 = (const float4*)h_sm;
    const size_t vrow_off = (size_t)(jbase + r16) * HH + (size_t)l16 * 16;

    uint4 v0 = *(const uint4*)(g_Vh + (size_t)(b * TT) * NTOT + vrow_off);
    uint4 v1 = *(const uint4*)(g_Vh + (size_t)(b * TT) * NTOT + vrow_off + 8);

    for (int step = 0; step < TT; step++) {
        const int mrow = b * TT + step;
        float wx = 0.f;
        if (qt == 0) wx = g_Wx[(size_t)mrow * GG + row];

        float acc = 0.f;
#pragma unroll
        for (int i = 0; i < 16; i++) {
            float4 hh = h4[i * 4 + qt];
            float4 uu = U4[i];
            acc += hh.x * uu.x + hh.y * uu.y + hh.z * uu.z + hh.w * uu.w;
        }
        acc += __shfl_xor_sync(0xffffffffu, acc, 1);
        acc += __shfl_xor_sync(0xffffffffu, acc, 2);

        float macc = 0.f;
        {
            const __half2* vh0 = (const __half2*)&v0;
            const __half2* vh1 = (const __half2*)&v1;
            float4 ha = h4[l16 * 4 + 0];
            float4 hbv = h4[l16 * 4 + 1];
            float4 hc = h4[l16 * 4 + 2];
            float4 hd = h4[l16 * 4 + 3];
            float2 p;
            p = __half22float2(vh0[0]); macc += p.x * ha.x  + p.y * ha.y;
            p = __half22float2(vh0[1]); macc += p.x * ha.z  + p.y * ha.w;
            p = __half22float2(vh0[2]); macc += p.x * hbv.x + p.y * hbv.y;
            p = __half22float2(vh0[3]); macc += p.x * hbv.z + p.y * hbv.w;
            p = __half22float2(vh1[0]); macc += p.x * hc.x  + p.y * hc.y;
            p = __half22float2(vh1[1]); macc += p.x * hc.z  + p.y * hc.w;
            p = __half22float2(vh1[2]); macc += p.x * hd.x  + p.y * hd.y;
            p = __half22float2(vh1[3]); macc += p.x * hd.z  + p.y * hd.w;
        }
        const int nrow = (step + 1 < TT) ? (mrow + 1) : mrow;
        v0 = *(const uint4*)(g_Vh + (size_t)nrow * NTOT + vrow_off);
        v1 = *(const uint4*)(g_Vh + (size_t)nrow * NTOT + vrow_off + 8);

#pragma unroll
        for (int off = 8; off > 0; off >>= 1)
            macc += __shfl_xor_sync(0xffffffffu, macc, off);

        if (qt == 0)  gates_sm[lg] = acc + wx + ub;
        if (l16 == 0) m_sm[r16] = macc;
        __syncthreads();

        if (t < 32) {
            const int j = jbase + t;
            const float gi = gates_sm[t];
            const float gf = gates_sm[32 + t];
            const float go = gates_sm[64 + t];
            const float gg = gates_sm[96 + t];
            const float iv = 1.f / (1.f + __expf(-gi));
            const float fv = 1.f / (1.f + __expf(-gf));
            const float ov = 1.f / (1.f + __expf(-go));
            const float gv = tanhf(gg);
            const float mv = tanhf(m_sm[t] + bb_sm[t]);
            const float c  = fv * c_sm[t] + iv * gv + SCALE_ * mv;
            c_sm[t] = c;
            const float hn = ov * tanhf(c);
            g_hbuf[step & 1][b][j] = hn;
            out[((size_t)b * TT + step) * HH + j] = hn;
            if (step == TT - 1) {
                const size_t base = (size_t)BB * TT * HH;
                out[base + (size_t)b * HH + j] = hn;
                out[base + (size_t)BB * HH + (size_t)b * HH + j] = c;
            }
            __threadfence();
        }

        asm volatile("barrier.cluster.arrive.aligned;" ::: "memory");
        asm volatile("barrier.cluster.wait.aligned;"   ::: "memory");
        if (t < HH) h_sm[t] = g_hbuf[step & 1][b][t];
        __syncthreads();
    }
}

// ===========================================================================
// Launcher
// ===========================================================================
extern "C" void kernel_launch(void* const* d_in, const int* in_sizes, int n_in,
                              void* d_out, int out_size)
{
    (void)in_sizes; (void)n_in; (void)out_size;
    const float* x   = (const float*)d_in[0];
    const float* Ww  = (const float*)d_in[1];
    const float* Wb  = (const float*)d_in[2];
    const float* Uw  = (const float*)d_in[3];
    const float* Ub  = (const float*)d_in[4];
    const float* Bw  = (const float*)d_in[5];
    const float* Bb  = (const float*)d_in[6];
    float* out = (float*)d_out;

    cudaFuncSetAttribute(gemm_v_mma,
                         cudaFuncAttributeMaxDynamicSharedMemorySize, VSMEM);

    conv_x_kernel<<<1024, 256>>>((const float2*)x);
    transB_kernel<<<dim3(8, 8, 256), dim3(32, 8)>>>(Bw);
    gemm_wx_kernel<<<dim3(GG / 128, (BB * TT) / 128), 256>>>(x, Ww, Wb);
    gemm_v_mma<<<dim3(8192 / VBM, NTOT / VBN), 256, VSMEM>>>();
    scan_kernel<<<dim3(8, BB), 512>>>(Uw, Ub, Bb, out);
}

// round 9
// speedup vs baseline: 2.5714x; 1.0998x over previous
#include <cuda_runtime.h>
#include <cuda_fp16.h>
#include <cstdint>
#include <cstddef>

#define BB 16
#define TT 512
#define DD 256
#define HH 256
#define GG 1024
#define NTOT 65536
#define SCALE_ 0.1f

// ---------------- scratch (device globals, no cudaMalloc) ----------------
__device__ float  g_Wx[(size_t)BB * TT * GG];        // 32 MB
__device__ __half g_Vh[(size_t)BB * TT * NTOT];      // 1 GB fp16 V
__device__ __half g_xh[(size_t)BB * TT * DD];        // 4 MB  x in half
__device__ __half g_Bh[(size_t)HH * HH * DD];        // 32 MB B_w as [o][h'][d]

// ---------------- helpers ----------------
__device__ __forceinline__ uint32_t smem_u32(const void* p) {
    return (uint32_t)__cvta_generic_to_shared(p);
}
__device__ __forceinline__ void cp16s(uint32_t dst, const void* src) {
    asm volatile("cp.async.cg.shared.global [%0], [%1], 16;" :: "r"(dst), "l"(src));
}
__device__ __forceinline__ void ldsm4(uint32_t* r, uint32_t a) {
    asm volatile("ldmatrix.sync.aligned.m8n8.x4.shared.b16 {%0,%1,%2,%3}, [%4];"
        : "=r"(r[0]), "=r"(r[1]), "=r"(r[2]), "=r"(r[3]) : "r"(a));
}
__device__ __forceinline__ void mma16816(float* d, const uint32_t* a, const uint32_t* b) {
    asm volatile(
        "mma.sync.aligned.m16n8k16.row.col.f32.f16.f16.f32 "
        "{%0,%1,%2,%3}, {%4,%5,%6,%7}, {%8,%9}, {%0,%1,%2,%3};\n"
        : "+f"(d[0]), "+f"(d[1]), "+f"(d[2]), "+f"(d[3])
        : "r"(a[0]), "r"(a[1]), "r"(a[2]), "r"(a[3]), "r"(b[0]), "r"(b[1]));
}
// store a float into the same smem offset of cluster CTA `rank`
#define ST_CL_F32(laddr, rank, val)                                          \
    asm volatile("{\n\t.reg .b32 ra;\n\t"                                    \
                 "mapa.shared::cluster.u32 ra, %0, %1;\n\t"                  \
                 "st.shared::cluster.f32 [ra], %2;\n\t}"                     \
                 :: "r"(laddr), "r"(rank), "f"(val) : "memory")

__device__ __forceinline__ float fsigm(float x) {
    return __fdividef(1.f, 1.f + __expf(-x));
}
__device__ __forceinline__ float ftanh(float x) {
    return __fdividef(2.f, 1.f + __expf(-2.f * x)) - 1.f;
}

// ---------------- prep: x -> half ----------------
__global__ void conv_x_kernel(const float2* __restrict__ src) {
    __half2* dst = (__half2*)g_xh;
    const int n2 = BB * TT * DD / 2;
    for (int i = blockIdx.x * blockDim.x + threadIdx.x; i < n2;
         i += gridDim.x * blockDim.x) {
        float2 v = src[i];
        dst[i] = __floats2half2_rn(v.x, v.y);
    }
}

// ---------------- prep: B_w [o][d][h] f32 -> g_Bh [o][h][d] half ----------------
__global__ void transB_kernel(const float* __restrict__ Bw) {
    __shared__ float tile[32][33];
    const int o  = blockIdx.z;
    const int d0 = blockIdx.y * 32;
    const int h0 = blockIdx.x * 32;
    const int tx = threadIdx.x, ty = threadIdx.y;
    const float* src = Bw + (size_t)o * NTOT;
#pragma unroll
    for (int i = 0; i < 4; i++)
        tile[ty + i * 8][tx] = src[(size_t)(d0 + ty + i * 8) * HH + h0 + tx];
    __syncthreads();
    __half* dst = g_Bh + (size_t)o * NTOT;
#pragma unroll
    for (int i = 0; i < 4; i++)
        dst[(size_t)(h0 + ty + i * 8) * DD + d0 + tx] =
            __float2half_rn(tile[tx][ty + i * 8]);
}

// ===========================================================================
// HMMA V GEMM (unchanged from R7: 866us, tensor 52.6%).
// Tile 256x128, BK=64, SW128 swizzle, 3-stage cp.async, ldmatrix.x4.
// ===========================================================================
#define VBM 256
#define VBN 128
#define ASTG (VBM * 128)
#define BSTG (VBN * 128)
#define STG  (ASTG + BSTG)
#define VSMEM (3 * STG)

__global__ void __launch_bounds__(256, 1) gemm_v_mma(void) {
    extern __shared__ char smem[];
    const uint32_t sb = smem_u32(smem);
    const int tid  = threadIdx.x;
    const int lane = tid & 31;
    const int w    = tid >> 5;

    const int m0 = blockIdx.x * VBM;
    const int n0 = blockIdx.y * VBN;
    const __half* Ag = g_xh + (size_t)m0 * DD;
    const __half* Bg = g_Bh + (size_t)n0 * DD;

    const int wm = (w & 3) * 64;
    const int wn = (w >> 2) * 64;

    const int a_row = wm + (lane & 15);
    const int a_rx  = ((a_row & 7) * 16);
    const int a_xo  = ((lane >> 4) & 1) * 16;
    const int b_row = wn + (lane & 7) + ((lane >> 4) & 1) * 8;
    const int b_rx  = ((b_row & 7) * 16);
    const int b_xo  = ((lane >> 3) & 1) * 16;

    float acc[4][8][4];
#pragma unroll
    for (int i = 0; i < 4; i++)
#pragma unroll
        for (int j = 0; j < 8; j++)
#pragma unroll
            for (int e = 0; e < 4; e++) acc[i][j][e] = 0.f;

    auto load_stage = [&](int kc, int stg) {
        const uint32_t sA = sb + stg * STG;
        const uint32_t sB = sA + ASTG;
        const __half* As = Ag + kc * 64;
        const __half* Bs2 = Bg + kc * 64;
#pragma unroll
        for (int i = 0; i < 8; i++) {
            const int idx = tid + 256 * i;
            const int r = idx >> 3, c = idx & 7;
            const uint32_t d = r * 128 + ((c * 16) ^ ((r & 7) * 16));
            cp16s(sA + d, As + (size_t)r * DD + c * 8);
        }
#pragma unroll
        for (int i = 0; i < 4; i++) {
            const int idx = tid + 256 * i;
            const int r = idx >> 3, c = idx & 7;
            const uint32_t d = r * 128 + ((c * 16) ^ ((r & 7) * 16));
            cp16s(sB + d, Bs2 + (size_t)r * DD + c * 8);
        }
        asm volatile("cp.async.commit_group;");
    };

    load_stage(0, 0);
    load_stage(1, 1);

#pragma unroll
    for (int kc = 0; kc < 4; kc++) {
        if (kc < 3) asm volatile("cp.async.wait_group 1;");
        else        asm volatile("cp.async.wait_group 0;");
        __syncthreads();
        if (kc < 2) load_stage(kc + 2, (kc + 2) % 3);

        const uint32_t sA = sb + (kc % 3) * STG;
        const uint32_t sB = sA + ASTG;
#pragma unroll
        for (int ks = 0; ks < 4; ks++) {
            uint32_t afr[4][4], bfr[4][4];
#pragma unroll
            for (int mt = 0; mt < 4; mt++) {
                const int r = a_row + mt * 16;
                ldsm4(afr[mt], sA + r * 128 + ((ks * 32 + a_xo) ^ a_rx));
            }
#pragma unroll
            for (int nt2 = 0; nt2 < 4; nt2++) {
                const int r = b_row + nt2 * 16;
                ldsm4(bfr[nt2], sB + r * 128 + ((ks * 32 + b_xo) ^ b_rx));
            }
#pragma unroll
            for (int mt = 0; mt < 4; mt++)
#pragma unroll
                for (int nt = 0; nt < 8; nt++)
                    mma16816(acc[mt][nt], afr[mt], &bfr[nt >> 1][(nt & 1) * 2]);
        }
        __syncthreads();
    }

    const int fr = lane >> 2, fq = (lane & 3) * 2;
#pragma unroll
    for (int mt = 0; mt < 4; mt++) {
        const int mA = m0 + wm + mt * 16 + fr;
#pragma unroll
        for (int nt = 0; nt < 8; nt++) {
            const int col = n0 + wn + nt * 8 + fq;
            *(__half2*)&g_Vh[(size_t)mA * NTOT + col] =
                __floats2half2_rn(acc[mt][nt][0], acc[mt][nt][1]);
            *(__half2*)&g_Vh[(size_t)(mA + 8) * NTOT + col] =
                __floats2half2_rn(acc[mt][nt][2], acc[mt][nt][3]);
        }
    }
}

// ===========================================================================
// GEMM 2 (fp32 SIMT): Wx = x @ W^T + b  (unchanged)
// ===========================================================================
__global__ __launch_bounds__(256) void gemm_wx_kernel(
    const float* __restrict__ A, const float* __restrict__ Ww,
    const float* __restrict__ Wb)
{
    __shared__ float As[2][16 * 132];
    __shared__ float Bs[2][16 * 132];
    const int tid = threadIdx.x;
    const int n0  = blockIdx.x * 128;
    const int m0  = blockIdx.y * 128;
    const int am = tid >> 1, ah = (tid & 1) * 8;
    const int tx = tid & 15, ty = tid >> 4;
    const float* Aptr = A  + (size_t)(m0 + am) * DD + ah;
    const float* Wptr = Ww + (size_t)(n0 + am) * DD + ah;

    float4 a0r = *(const float4*)(Aptr);
    float4 a1r = *(const float4*)(Aptr + 4);
    float4 b0r = *(const float4*)(Wptr);
    float4 b1r = *(const float4*)(Wptr + 4);

    float acc[8][8];
#pragma unroll
    for (int i = 0; i < 8; i++)
#pragma unroll
        for (int j = 0; j < 8; j++) acc[i][j] = 0.f;

    {
        float av[8] = {a0r.x,a0r.y,a0r.z,a0r.w,a1r.x,a1r.y,a1r.z,a1r.w};
        float bv[8] = {b0r.x,b0r.y,b0r.z,b0r.w,b1r.x,b1r.y,b1r.z,b1r.w};
#pragma unroll
        for (int i = 0; i < 8; i++) {
            As[0][(ah + i) * 132 + am] = av[i];
            Bs[0][(ah + i) * 132 + am] = bv[i];
        }
    }
    __syncthreads();

    int p = 0;
#pragma unroll 1
    for (int s = 0; s < 16; s++) {
        if (s < 15) {
            const int k0 = (s + 1) * 16;
            a0r = *(const float4*)(Aptr + k0);
            a1r = *(const float4*)(Aptr + k0 + 4);
            b0r = *(const float4*)(Wptr + k0);
            b1r = *(const float4*)(Wptr + k0 + 4);
        }
#pragma unroll
        for (int kk = 0; kk < 16; kk++) {
            float4 a0 = *(const float4*)&As[p][kk * 132 + ty * 4];
            float4 a1 = *(const float4*)&As[p][kk * 132 + 64 + ty * 4];
            float4 b0 = *(const float4*)&Bs[p][kk * 132 + tx * 4];
            float4 b1 = *(const float4*)&Bs[p][kk * 132 + 64 + tx * 4];
            float ar[8] = {a0.x,a0.y,a0.z,a0.w,a1.x,a1.y,a1.z,a1.w};
            float br[8] = {b0.x,b0.y,b0.z,b0.w,b1.x,b1.y,b1.z,b1.w};
#pragma unroll
            for (int i = 0; i < 8; i++)
#pragma unroll
                for (int j = 0; j < 8; j++) acc[i][j] += ar[i] * br[j];
        }
        if (s < 15) {
            __syncthreads();
            const int q = p ^ 1;
            float av[8] = {a0r.x,a0r.y,a0r.z,a0r.w,a1r.x,a1r.y,a1r.z,a1r.w};
            float bv[8] = {b0r.x,b0r.y,b0r.z,b0r.w,b1r.x,b1r.y,b1r.z,b1r.w};
#pragma unroll
            for (int i = 0; i < 8; i++) {
                As[q][(ah + i) * 132 + am] = av[i];
                Bs[q][(ah + i) * 132 + am] = bv[i];
            }
            __syncthreads();
            p = q;
        }
    }

    float wb0[4], wb1[4];
#pragma unroll
    for (int j = 0; j < 4; j++) {
        wb0[j] = Wb[n0 + tx * 4 + j];
        wb1[j] = Wb[n0 + 64 + tx * 4 + j];
    }
#pragma unroll
    for (int i = 0; i < 8; i++) {
        const int rr = (i < 4) ? (ty * 4 + i) : (64 + ty * 4 + (i - 4));
        float* Wo = g_Wx + (size_t)(m0 + rr) * GG + n0;
        *(float4*)&Wo[tx * 4] = make_float4(acc[i][0] + wb0[0], acc[i][1] + wb0[1],
                                            acc[i][2] + wb0[2], acc[i][3] + wb0[3]);
        *(float4*)&Wo[64 + tx * 4] = make_float4(acc[i][4] + wb1[0], acc[i][5] + wb1[1],
                                                 acc[i][6] + wb1[2], acc[i][7] + wb1[3]);
    }
}

// ===========================================================================
// Scan v2: 8-CTA cluster per batch. h handoff via DSMEM push (mapa +
// st.shared::cluster) into a double-buffered h_sm; one cluster barrier and
// one __syncthreads per step; no threadfence, no global h buffer.
// ===========================================================================
__global__ void __cluster_dims__(8, 1, 1) __launch_bounds__(512, 1)
scan_kernel(const float* __restrict__ Uw, const float* __restrict__ Ub,
            const float* __restrict__ Bbias, float* __restrict__ out)
{
    __shared__ float h_sm[2][HH];
    __shared__ float gates_sm[128];
    __shared__ float m_sm[32];
    __shared__ float c_sm[32];
    __shared__ float bb_sm[32];

    const int r     = blockIdx.x;
    const int b     = blockIdx.y;
    const int jbase = r * 32;
    const int t     = threadIdx.x;
    const int qt    = t & 3;
    const int lg    = t >> 2;
    const int row   = (lg >> 5) * HH + jbase + (lg & 31);
    const int r16   = t >> 4;
    const int l16   = t & 15;

    float4 U4[16];
#pragma unroll
    for (int i = 0; i < 16; i++)
        U4[i] = *(const float4*)&Uw[(size_t)row * HH + (size_t)(i * 4 + qt) * 4];
    const float ub = Ub[row];

    if (t < HH)  h_sm[0][t] = 0.f;
    if (t < 32) { c_sm[t] = 0.f; bb_sm[t] = Bbias[jbase + t]; }
    __syncthreads();

    const size_t vrow_off = (size_t)(jbase + r16) * HH + (size_t)l16 * 16;
    uint4 v0 = *(const uint4*)(g_Vh + (size_t)(b * TT) * NTOT + vrow_off);
    uint4 v1 = *(const uint4*)(g_Vh + (size_t)(b * TT) * NTOT + vrow_off + 8);

    for (int step = 0; step < TT; step++) {
        const int p = step & 1;
        const float4* h4 = (const float4*)h_sm[p];
        const int mrow = b * TT + step;

        float wx = 0.f;
        if (qt == 0) wx = g_Wx[(size_t)mrow * GG + row];

        // gates: dot(U_row, h), split over 4 lanes
        float acc = 0.f;
#pragma unroll
        for (int i = 0; i < 16; i++) {
            float4 hh = h4[i * 4 + qt];
            float4 uu = U4[i];
            acc += hh.x * uu.x + hh.y * uu.y + hh.z * uu.z + hh.w * uu.w;
        }
        acc += __shfl_xor_sync(0xffffffffu, acc, 1);
        acc += __shfl_xor_sync(0xffffffffu, acc, 2);

        // m: dot(V_row fp16, h), split over 16 lanes
        float macc = 0.f;
        {
            const __half2* vh0 = (const __half2*)&v0;
            const __half2* vh1 = (const __half2*)&v1;
            float4 ha  = h4[l16 * 4 + 0];
            float4 hbv = h4[l16 * 4 + 1];
            float4 hc  = h4[l16 * 4 + 2];
            float4 hd  = h4[l16 * 4 + 3];
            float2 pp;
            pp = __half22float2(vh0[0]); macc += pp.x * ha.x  + pp.y * ha.y;
            pp = __half22float2(vh0[1]); macc += pp.x * ha.z  + pp.y * ha.w;
            pp = __half22float2(vh0[2]); macc += pp.x * hbv.x + pp.y * hbv.y;
            pp = __half22float2(vh0[3]); macc += pp.x * hbv.z + pp.y * hbv.w;
            pp = __half22float2(vh1[0]); macc += pp.x * hc.x  + pp.y * hc.y;
            pp = __half22float2(vh1[1]); macc += pp.x * hc.z  + pp.y * hc.w;
            pp = __half22float2(vh1[2]); macc += pp.x * hd.x  + pp.y * hd.y;
            pp = __half22float2(vh1[3]); macc += pp.x * hd.z  + pp.y * hd.w;
        }
        // prefetch next step's V (h-independent)
        const int nrow = (step + 1 < TT) ? (mrow + 1) : mrow;
        v0 = *(const uint4*)(g_Vh + (size_t)nrow * NTOT + vrow_off);
        v1 = *(const uint4*)(g_Vh + (size_t)nrow * NTOT + vrow_off + 8);

#pragma unroll
        for (int off = 8; off > 0; off >>= 1)
            macc += __shfl_xor_sync(0xffffffffu, macc, off);

        if (qt == 0)  gates_sm[lg] = acc + wx + ub;
        if (l16 == 0) m_sm[r16] = macc;
        __syncthreads();

        if (t < 32) {
            const int j = jbase + t;
            const float iv = fsigm(gates_sm[t]);
            const float fv = fsigm(gates_sm[32 + t]);
            const float ov = fsigm(gates_sm[64 + t]);
            const float gv = ftanh(gates_sm[96 + t]);
            const float mv = ftanh(m_sm[t] + bb_sm[t]);
            const float c  = fv * c_sm[t] + iv * gv + SCALE_ * mv;
            c_sm[t] = c;
            const float hn = ov * ftanh(c);
            out[((size_t)b * TT + step) * HH + j] = hn;
            if (step == TT - 1) {
                const size_t base = (size_t)BB * TT * HH;
                out[base + (size_t)b * HH + j] = hn;
                out[base + (size_t)BB * HH + (size_t)b * HH + j] = c;
            }
            // push hn into next-step buffer of all 8 cluster CTAs
            const uint32_t la = smem_u32(&h_sm[p ^ 1][j]);
#pragma unroll
            for (int k = 0; k < 8; k++) ST_CL_F32(la, k, hn);
        }

        // cluster handoff (release/acquire orders the DSMEM stores);
        // wait is also a full CTA barrier, so no extra __syncthreads.
        asm volatile("barrier.cluster.arrive.aligned;" ::: "memory");
        asm volatile("barrier.cluster.wait.aligned;"   ::: "memory");
    }
}

// ===========================================================================
// Launcher
// ===========================================================================
extern "C" void kernel_launch(void* const* d_in, const int* in_sizes, int n_in,
                              void* d_out, int out_size)
{
    (void)in_sizes; (void)n_in; (void)out_size;
    const float* x   = (const float*)d_in[0];
    const float* Ww  = (const float*)d_in[1];
    const float* Wb  = (const float*)d_in[2];
    const float* Uw  = (const float*)d_in[3];
    const float* Ub  = (const float*)d_in[4];
    const float* Bw  = (const float*)d_in[5];
    const float* Bb  = (const float*)d_in[6];
    float* out = (float*)d_out;

    cudaFuncSetAttribute(gemm_v_mma,
                         cudaFuncAttributeMaxDynamicSharedMemorySize, VSMEM);

    conv_x_kernel<<<1024, 256>>>((const float2*)x);
    transB_kernel<<<dim3(8, 8, 256), dim3(32, 8)>>>(Bw);
    gemm_wx_kernel<<<dim3(GG / 128, (BB * TT) / 128), 256>>>(x, Ww, Wb);
    gemm_v_mma<<<dim3(8192 / VBM, NTOT / VBN), 256, VSMEM>>>();
    scan_kernel<<<dim3(8, BB), 512>>>(Uw, Ub, Bb, out);
}